// round 3
// baseline (speedup 1.0000x reference)
#include <cuda_runtime.h>
#include <cuda_fp16.h>
#include <cstdint>

// Problem constants
#define B_SZ   32768
#define N_VARS 64
#define H_SZ   64
#define N_DISC 16
#define TILE_M 128          // batch rows per CTA
#define G_NODES 8           // nodes per CTA
#define NODE_GROUPS 8       // 64 / 8
#define BTILES (B_SZ / TILE_M)   // 256

// X tile in smem: fp16, padded row stride 72 halves (144B) -> conflict-free ldmatrix
#define XS_STRIDE 72

// smem layout (bytes)
#define SM_X    0
#define SM_X_SZ (TILE_M * XS_STRIDE * 2)                 // 18432
#define SM_W    ((SM_X + SM_X_SZ + 15) & ~15)            // 18432
#define SM_W_SZ (G_NODES * 4 * 8 * 32 * 8)               // 65536 (uint2 frags)
#define SM_W2   (SM_W + SM_W_SZ)                         // 83968
#define SM_W2_SZ (G_NODES * H_SZ * 4)                    // 2048
#define SM_OUT  (SM_W2 + SM_W2_SZ)                       // 86016
#define SM_OUT_SZ (TILE_M * G_NODES * 4)                 // 4096
#define SM_TOTAL (SM_OUT + SM_OUT_SZ)                    // 90112

// Pre-swizzled fp16 B fragments: [node][ktile(4)][ntile(8)][lane(32)] x uint2
__device__ uint2 g_wfrag[(size_t)N_VARS * 4 * 8 * 32];

__device__ __forceinline__ uint32_t h2_as_u32(__half2 h) {
    union { __half2 h; uint32_t u; } cvt;
    cvt.h = h;
    return cvt.u;
}

__device__ __forceinline__ uint32_t smem_u32(const void* p) {
    uint32_t a;
    asm("{ .reg .u64 t; cvta.to.shared.u64 t, %1; cvt.u32.u64 %0, t; }" : "=r"(a) : "l"(p));
    return a;
}

__device__ __forceinline__ void ldmatrix_x4(uint32_t r[4], uint32_t addr) {
    asm volatile("ldmatrix.sync.aligned.m8n8.x4.shared.b16 {%0,%1,%2,%3}, [%4];"
                 : "=r"(r[0]), "=r"(r[1]), "=r"(r[2]), "=r"(r[3]) : "r"(addr));
}

__device__ __forceinline__ void mma16816(float c[4], const uint32_t a[4],
                                         uint32_t b0, uint32_t b1) {
    asm volatile(
        "mma.sync.aligned.m16n8k16.row.col.f32.f16.f16.f32 "
        "{%0,%1,%2,%3}, {%4,%5,%6,%7}, {%8,%9}, {%0,%1,%2,%3};"
        : "+f"(c[0]), "+f"(c[1]), "+f"(c[2]), "+f"(c[3])
        : "r"(a[0]), "r"(a[1]), "r"(a[2]), "r"(a[3]), "r"(b0), "r"(b1));
}

// ---------------- prolog: build masked fp16 B fragments ----------------
// B[k][n] = W1m[node][h=n][var=k]; frag: b0,b1 = k0,k0+1; b2,b3 = k0+8,k0+9
// with k0 = ktile*16 + (lane%4)*2, n = ntile*8 + lane/4
__global__ void __launch_bounds__(256) wfrag_kernel(const float* __restrict__ W1,
                                                    const float* __restrict__ adj) {
    int idx = blockIdx.x * 256 + threadIdx.x;        // 65536 total
    int lane  = idx & 31;
    int ntile = (idx >> 5) & 7;
    int ktile = (idx >> 8) & 3;
    int node  = idx >> 10;
    int h  = ntile * 8 + (lane >> 2);
    int k0 = ktile * 16 + (lane & 3) * 2;

    const float* wrow = W1 + ((size_t)node * H_SZ + h) * N_VARS;
    float2 wlo = *(const float2*)(wrow + k0);
    float2 whi = *(const float2*)(wrow + k0 + 8);
    const float* arow = adj + node * N_VARS;
    float2 alo = *(const float2*)(arow + k0);
    float2 ahi = *(const float2*)(arow + k0 + 8);
    if (node == N_VARS - 1) {   // hidden_flag: last node keeps only feature 63
        alo.x = 0.f; alo.y = 0.f;
        ahi.x = 0.f;
        if (k0 + 9 != N_VARS - 1) ahi.y = 0.f;
    }
    uint2 r;
    r.x = h2_as_u32(__floats2half2_rn(wlo.x * alo.x, wlo.y * alo.y));
    r.y = h2_as_u32(__floats2half2_rn(whi.x * ahi.x, whi.y * ahi.y));
    g_wfrag[idx] = r;
}

// ---------------- main kernel ----------------
__global__ void __launch_bounds__(256, 2)
main_kernel(const float4* __restrict__ in4, const float* __restrict__ W2,
            float* __restrict__ out) {
    extern __shared__ char smem[];
    const int tid = threadIdx.x;
    const int lane = tid & 31, warp = tid >> 5;
    const int group = blockIdx.y;
    const int row0 = blockIdx.x * TILE_M;

    __half2* xs = (__half2*)(smem + SM_X);
    uint2* ws = (uint2*)(smem + SM_W);
    float* w2s = (float*)(smem + SM_W2);
    float* outs = (float*)(smem + SM_OUT);

    // --- load B fragments for this node group (64KB, bulk copy from L2) ---
    {
        const uint4* src = (const uint4*)(g_wfrag + (size_t)group * G_NODES * 4 * 8 * 32);
        uint4* dst = (uint4*)ws;
#pragma unroll
        for (int it = 0; it < 16; it++)
            dst[tid + it * 256] = src[tid + it * 256];
    }
    // --- W2 for this group (512 floats) ---
    if (tid < 128)
        ((float4*)w2s)[tid] = ((const float4*)(W2 + group * G_NODES * H_SZ))[tid];

    // --- load X tile, apply straight-through gate, convert fp16 ---
    // 128 rows x 16 float4; vars 0..15 are discrete (j<4)
#pragma unroll
    for (int it = 0; it < 8; it++) {
        int idx = tid + it * 256;             // 0..2047
        int r = idx >> 4, j = idx & 15;
        float4 v = in4[(size_t)(row0 + r) * 16 + j];
        if (j < 4) {
            v.x = v.x > 0.f ? 1.f : 0.f;
            v.y = v.y > 0.f ? 1.f : 0.f;
            v.z = v.z > 0.f ? 1.f : 0.f;
            v.w = v.w > 0.f ? 1.f : 0.f;
        }
        xs[r * (XS_STRIDE / 2) + j * 2]     = __floats2half2_rn(v.x, v.y);
        xs[r * (XS_STRIDE / 2) + j * 2 + 1] = __floats2half2_rn(v.z, v.w);
    }
    __syncthreads();

    // --- A fragments: 16 rows per warp, all K=64 (4 ktiles) ---
    const uint32_t xsb = smem_u32(smem) + SM_X;
    const int wr0 = warp * 16;
    const int mtx = lane >> 3, rowm = lane & 7;
    uint32_t afr[4][4];
#pragma unroll
    for (int kt = 0; kt < 4; kt++) {
        uint32_t addr = xsb + (uint32_t)((wr0 + (mtx & 1) * 8 + rowm) * (XS_STRIDE * 2)
                                         + (kt * 16 + (mtx >> 1) * 8) * 2);
        ldmatrix_x4(afr[kt], addr);
    }

    // --- node loop ---
    const uint32_t wsb = smem_u32(smem) + SM_W;
    const int lq = lane & 3;       // quad col id
    const int lr = lane >> 2;      // row-in-8
#pragma unroll 1
    for (int jg = 0; jg < G_NODES; jg++) {
        float acc[8][4];
#pragma unroll
        for (int nt = 0; nt < 8; nt++)
#pragma unroll
            for (int q = 0; q < 4; q++) acc[nt][q] = 0.f;

#pragma unroll
        for (int kt = 0; kt < 4; kt++) {
            uint32_t base = wsb + (uint32_t)(((jg * 4 + kt) * 8 * 32 + lane) * 8);
            uint2 bf[8];
#pragma unroll
            for (int nt = 0; nt < 8; nt++)
                asm volatile("ld.shared.v2.u32 {%0,%1}, [%2];"
                             : "=r"(bf[nt].x), "=r"(bf[nt].y)
                             : "r"(base + nt * 256));
#pragma unroll
            for (int nt = 0; nt < 8; nt++)
                mma16816(acc[nt], afr[kt], bf[nt].x, bf[nt].y);
        }

        // epilogue: relu + dot W2 over H, reduce across quad
        float s0 = 0.f, s1 = 0.f;
#pragma unroll
        for (int nt = 0; nt < 8; nt++) {
            float2 w2v = *(const float2*)&w2s[jg * H_SZ + nt * 8 + lq * 2];
            s0 = fmaf(fmaxf(acc[nt][0], 0.f), w2v.x, s0);
            s0 = fmaf(fmaxf(acc[nt][1], 0.f), w2v.y, s0);
            s1 = fmaf(fmaxf(acc[nt][2], 0.f), w2v.x, s1);
            s1 = fmaf(fmaxf(acc[nt][3], 0.f), w2v.y, s1);
        }
        s0 += __shfl_xor_sync(0xFFFFFFFF, s0, 1);
        s0 += __shfl_xor_sync(0xFFFFFFFF, s0, 2);
        s1 += __shfl_xor_sync(0xFFFFFFFF, s1, 1);
        s1 += __shfl_xor_sync(0xFFFFFFFF, s1, 2);
        if (lq == 0) {
            outs[(wr0 + lr) * G_NODES + jg] = s0;
            outs[(wr0 + lr + 8) * G_NODES + jg] = s1;
        }
    }
    __syncthreads();

    // --- coalesced store: 128 rows x 8 floats = 256 float4 ---
    {
        int r = tid >> 1, q = tid & 1;
        float4 v = ((const float4*)outs)[tid];
        *(float4*)(out + (size_t)(row0 + r) * N_VARS + group * G_NODES + q * 4) = v;
    }
}

// ---------------- launch ----------------
extern "C" void kernel_launch(void* const* d_in, const int* in_sizes, int n_in,
                              void* d_out, int out_size) {
    // metadata order: t, inputs, W1, W2, adjacency, discrete_mask
    const float* inputs = (const float*)d_in[1];
    const float* W1     = (const float*)d_in[2];
    const float* W2     = (const float*)d_in[3];
    const float* adj    = (const float*)d_in[4];
    float* out = (float*)d_out;

    static bool attr_set = false;
    if (!attr_set) {
        cudaFuncSetAttribute(main_kernel, cudaFuncAttributeMaxDynamicSharedMemorySize,
                             SM_TOTAL);
        attr_set = true;
    }

    wfrag_kernel<<<256, 256>>>(W1, adj);
    main_kernel<<<dim3(BTILES, NODE_GROUPS), 256, SM_TOTAL>>>(
        (const float4*)inputs, W2, out);
}

// round 4
// speedup vs baseline: 1.3571x; 1.3571x over previous
#include <cuda_runtime.h>
#include <cuda_fp16.h>
#include <cstdint>

// Problem constants
#define B_SZ   32768
#define N_VARS 64
#define H_SZ   64
#define TILE_M 256          // batch rows per CTA
#define G_NODES 8           // nodes per CTA (one per warp)
#define NODE_GROUPS 8       // 64 / 8
#define BTILES (B_SZ / TILE_M)   // 128
#define MTILES (TILE_M / 16)     // 16

// X tile in smem: fp16, padded row stride 72 halves (144B) -> conflict-free ldmatrix
#define XS_STRIDE 72

// smem layout (bytes)
#define SM_X    0
#define SM_X_SZ (TILE_M * XS_STRIDE * 2)                 // 36864
#define SM_W2   (SM_X + SM_X_SZ)                         // 36864
#define SM_W2_SZ (G_NODES * H_SZ * 4)                    // 2048
#define SM_OUT  (SM_W2 + SM_W2_SZ)                       // 38912
#define SM_OUT_SZ (TILE_M * G_NODES * 4)                 // 8192
#define SM_TOTAL (SM_OUT + SM_OUT_SZ)                    // 47104

// Pre-swizzled fp16 B fragments: [node][ktile(4)][ntile(8)][lane(32)] x uint2
__device__ uint2 g_wfrag[(size_t)N_VARS * 4 * 8 * 32];

__device__ __forceinline__ uint32_t h2_as_u32(__half2 h) {
    union { __half2 h; uint32_t u; } cvt;
    cvt.h = h;
    return cvt.u;
}

__device__ __forceinline__ uint32_t smem_u32(const void* p) {
    uint32_t a;
    asm("{ .reg .u64 t; cvta.to.shared.u64 t, %1; cvt.u32.u64 %0, t; }" : "=r"(a) : "l"(p));
    return a;
}

__device__ __forceinline__ void ldmatrix_x4(uint32_t r[4], uint32_t addr) {
    asm volatile("ldmatrix.sync.aligned.m8n8.x4.shared.b16 {%0,%1,%2,%3}, [%4];"
                 : "=r"(r[0]), "=r"(r[1]), "=r"(r[2]), "=r"(r[3]) : "r"(addr));
}

__device__ __forceinline__ void mma16816(float c[4], const uint32_t a[4],
                                         uint32_t b0, uint32_t b1) {
    asm volatile(
        "mma.sync.aligned.m16n8k16.row.col.f32.f16.f16.f32 "
        "{%0,%1,%2,%3}, {%4,%5,%6,%7}, {%8,%9}, {%0,%1,%2,%3};"
        : "+f"(c[0]), "+f"(c[1]), "+f"(c[2]), "+f"(c[3])
        : "r"(a[0]), "r"(a[1]), "r"(a[2]), "r"(a[3]), "r"(b0), "r"(b1));
}

// ---------------- prolog: build masked fp16 B fragments ----------------
// B[k][n] = W1m[node][h=n][var=k]; frag: b0,b1 = k0,k0+1; b2,b3 = k0+8,k0+9
// with k0 = ktile*16 + (lane%4)*2, n = ntile*8 + lane/4
__global__ void __launch_bounds__(256) wfrag_kernel(const float* __restrict__ W1,
                                                    const float* __restrict__ adj) {
    int idx = blockIdx.x * 256 + threadIdx.x;        // 65536 total
    int lane  = idx & 31;
    int ntile = (idx >> 5) & 7;
    int ktile = (idx >> 8) & 3;
    int node  = idx >> 10;
    int h  = ntile * 8 + (lane >> 2);
    int k0 = ktile * 16 + (lane & 3) * 2;

    const float* wrow = W1 + ((size_t)node * H_SZ + h) * N_VARS;
    float2 wlo = *(const float2*)(wrow + k0);
    float2 whi = *(const float2*)(wrow + k0 + 8);
    const float* arow = adj + node * N_VARS;
    float2 alo = *(const float2*)(arow + k0);
    float2 ahi = *(const float2*)(arow + k0 + 8);
    if (node == N_VARS - 1) {   // hidden_flag: last node keeps only feature 63
        alo.x = 0.f; alo.y = 0.f;
        ahi.x = 0.f;
        if (k0 + 9 != N_VARS - 1) ahi.y = 0.f;
    }
    uint2 r;
    r.x = h2_as_u32(__floats2half2_rn(wlo.x * alo.x, wlo.y * alo.y));
    r.y = h2_as_u32(__floats2half2_rn(whi.x * ahi.x, whi.y * ahi.y));
    g_wfrag[idx] = r;
}

// ---------------- main kernel ----------------
// One warp == one node. B tile (64x64 fp16) lives in 64 registers per lane.
__global__ void __launch_bounds__(256, 2)
main_kernel(const float4* __restrict__ in4, const float* __restrict__ W2,
            float* __restrict__ out) {
    extern __shared__ char smem[];
    const int tid = threadIdx.x;
    const int lane = tid & 31, warp = tid >> 5;   // warp = node-in-group
    const int group = blockIdx.y;
    const int row0 = blockIdx.x * TILE_M;

    __half2* xs = (__half2*)(smem + SM_X);
    float* w2s = (float*)(smem + SM_W2);
    float* outs = (float*)(smem + SM_OUT);

    // --- B fragments for this warp's node: 64 regs (L2-resident source) ---
    uint2 bf[4][8];
    {
        const uint2* src = g_wfrag + ((size_t)(group * G_NODES + warp) * 4) * 8 * 32 + lane;
#pragma unroll
        for (int kt = 0; kt < 4; kt++)
#pragma unroll
            for (int nt = 0; nt < 8; nt++)
                bf[kt][nt] = src[(kt * 8 + nt) * 32];
    }

    // --- W2 for this group (512 floats) ---
    if (tid < 128)
        ((float4*)w2s)[tid] = ((const float4*)(W2 + group * G_NODES * H_SZ))[tid];

    // --- load X tile, apply straight-through gate, convert fp16 ---
    // 256 rows x 16 float4; vars 0..15 are discrete (j<4)
#pragma unroll
    for (int it = 0; it < 16; it++) {
        int idx = tid + it * 256;             // 0..4095
        int r = idx >> 4, j = idx & 15;
        float4 v = in4[(size_t)(row0 + r) * 16 + j];
        if (j < 4) {
            v.x = v.x > 0.f ? 1.f : 0.f;
            v.y = v.y > 0.f ? 1.f : 0.f;
            v.z = v.z > 0.f ? 1.f : 0.f;
            v.w = v.w > 0.f ? 1.f : 0.f;
        }
        xs[r * (XS_STRIDE / 2) + j * 2]     = __floats2half2_rn(v.x, v.y);
        xs[r * (XS_STRIDE / 2) + j * 2 + 1] = __floats2half2_rn(v.z, v.w);
    }
    __syncthreads();

    const uint32_t xsb = smem_u32(smem) + SM_X;
    const int mtx = lane >> 3, rowm = lane & 7;
    const int lq = lane & 3;       // quad col id
    const int lr = lane >> 2;      // row-in-8
    // ldmatrix base offset within a 16-row mtile (row part + col-ktile part added in loop)
    const uint32_t arow_off = (uint32_t)(((mtx & 1) * 8 + rowm) * (XS_STRIDE * 2)
                                         + ((mtx >> 1) * 8) * 2);

#pragma unroll 1
    for (int mt = 0; mt < MTILES; mt++) {
        const uint32_t mbase = xsb + (uint32_t)(mt * 16 * (XS_STRIDE * 2)) + arow_off;

        float acc[8][4];
#pragma unroll
        for (int nt = 0; nt < 8; nt++)
#pragma unroll
            for (int q = 0; q < 4; q++) acc[nt][q] = 0.f;

        uint32_t a0[4], a1[4];
        ldmatrix_x4(a0, mbase);
#pragma unroll
        for (int kt = 0; kt < 4; kt++) {
            uint32_t* acur = (kt & 1) ? a1 : a0;
            uint32_t* anxt = (kt & 1) ? a0 : a1;
            if (kt < 3) ldmatrix_x4(anxt, mbase + (uint32_t)((kt + 1) * 16 * 2));
#pragma unroll
            for (int nt = 0; nt < 8; nt++)
                mma16816(acc[nt], acur, bf[kt][nt].x, bf[kt][nt].y);
        }

        // epilogue: relu + dot W2 over H, reduce across quad
        float s0 = 0.f, s1 = 0.f;
#pragma unroll
        for (int nt = 0; nt < 8; nt++) {
            float2 w2v = *(const float2*)&w2s[warp * H_SZ + nt * 8 + lq * 2];
            s0 = fmaf(fmaxf(acc[nt][0], 0.f), w2v.x, s0);
            s0 = fmaf(fmaxf(acc[nt][1], 0.f), w2v.y, s0);
            s1 = fmaf(fmaxf(acc[nt][2], 0.f), w2v.x, s1);
            s1 = fmaf(fmaxf(acc[nt][3], 0.f), w2v.y, s1);
        }
        s0 += __shfl_xor_sync(0xFFFFFFFF, s0, 1);
        s0 += __shfl_xor_sync(0xFFFFFFFF, s0, 2);
        s1 += __shfl_xor_sync(0xFFFFFFFF, s1, 1);
        s1 += __shfl_xor_sync(0xFFFFFFFF, s1, 2);
        if (lq == 0) {
            outs[(mt * 16 + lr) * G_NODES + warp] = s0;
            outs[(mt * 16 + lr + 8) * G_NODES + warp] = s1;
        }
    }
    __syncthreads();

    // --- coalesced store: 256 rows x 8 floats = 512 float4 ---
#pragma unroll
    for (int it = 0; it < 2; it++) {
        int idx = tid + it * 256;
        int r = idx >> 1, q = idx & 1;
        float4 v = ((const float4*)outs)[idx];
        *(float4*)(out + (size_t)(row0 + r) * N_VARS + group * G_NODES + q * 4) = v;
    }
}

// ---------------- launch ----------------
extern "C" void kernel_launch(void* const* d_in, const int* in_sizes, int n_in,
                              void* d_out, int out_size) {
    // metadata order: t, inputs, W1, W2, adjacency, discrete_mask
    const float* inputs = (const float*)d_in[1];
    const float* W1     = (const float*)d_in[2];
    const float* W2     = (const float*)d_in[3];
    const float* adj    = (const float*)d_in[4];
    float* out = (float*)d_out;

    static bool attr_set = false;
    if (!attr_set) {
        cudaFuncSetAttribute(main_kernel, cudaFuncAttributeMaxDynamicSharedMemorySize,
                             SM_TOTAL);
        attr_set = true;
    }

    wfrag_kernel<<<256, 256>>>(W1, adj);
    main_kernel<<<dim3(BTILES, NODE_GROUPS), 256, SM_TOTAL>>>(
        (const float4*)inputs, W2, out);
}